// round 2
// baseline (speedup 1.0000x reference)
#include <cuda_runtime.h>

#define N_NODES 100000
#define N_EDGES 1600000
#define IN_C    512
#define HID_C   128
#define OUT_C   40

// ---------------- scratch (device globals; no allocations) ----------------
__device__ float g_deg[N_NODES];
__device__ int   g_src[N_EDGES];
__device__ int   g_dst[N_EDGES];
__device__ float g_w[N_EDGES];
__device__ float g_h0[N_NODES * HID_C];     // 51.2 MB
__device__ float g_agg0[N_NODES * HID_C];   // 51.2 MB
__device__ float g_h1[N_NODES * OUT_C];     // 16 MB

// ---------------- zero scratch + output ----------------
__global__ void zero_all(float4* __restrict__ out) {
    int i = blockIdx.x * blockDim.x + threadIdx.x;
    int stride = gridDim.x * blockDim.x;
    float4 z = make_float4(0.f, 0.f, 0.f, 0.f);
    float4* agg = (float4*)g_agg0;
    for (int j = i; j < N_NODES * HID_C / 4; j += stride) agg[j] = z;
    for (int j = i; j < N_NODES * OUT_C / 4; j += stride) out[j] = z;
    float4* dg = (float4*)g_deg;
    for (int j = i; j < N_NODES / 4; j += stride) dg[j] = z;
}

// ---------------- degree (in-degree over dst, as in reference) ----------------
// edge_index is int32 [2, N_EDGES]: src = ei[e], dst = ei[N_EDGES + e]
__global__ void deg_kernel(const int* __restrict__ ei) {
    int e = blockIdx.x * blockDim.x + threadIdx.x;
    if (e < N_EDGES) {
        unsigned d = (unsigned)ei[N_EDGES + e];
        if (d < N_NODES) atomicAdd(&g_deg[d], 1.0f);
    }
}

__global__ void dinv_kernel() {
    int i = blockIdx.x * blockDim.x + threadIdx.x;
    if (i < N_NODES) g_deg[i] = rsqrtf(fmaxf(g_deg[i], 1.0f));
}

// int32 indices copied + per-edge weight (shared by both conv layers)
__global__ void prep_kernel(const int* __restrict__ ei) {
    int e = blockIdx.x * blockDim.x + threadIdx.x;
    if (e < N_EDGES) {
        unsigned s = (unsigned)ei[e];
        unsigned d = (unsigned)ei[N_EDGES + e];
        if (s >= N_NODES) s = 0;   // safety: never fault, fail via rel_err instead
        if (d >= N_NODES) d = 0;
        g_src[e] = (int)s;
        g_dst[e] = (int)d;
        g_w[e] = g_deg[s] * g_deg[d];
    }
}

// ---------------- GEMM0: h0[N,128] = x[N,512] @ W0[128,512]^T ----------------
// BM=64, BN=128, BK=32, 256 threads, each thread 8x4 micro-tile.
#define BM 64
#define BN 128
#define BK 32
__global__ __launch_bounds__(256) void gemm0_kernel(const float* __restrict__ x,
                                                    const float* __restrict__ W0) {
    __shared__ float As[BK][BM];      // transposed A tile, 8 KB
    __shared__ float Bs[BK][BN];      // 16 KB
    int block_row = blockIdx.x * BM;
    int tid  = threadIdx.x;
    int tcol = tid & 31;              // 32 col-groups of 4
    int trow = tid >> 5;              // 8 row-groups of 8

    float acc[8][4];
#pragma unroll
    for (int i = 0; i < 8; i++)
#pragma unroll
        for (int j = 0; j < 4; j++) acc[i][j] = 0.f;

    for (int k0 = 0; k0 < IN_C; k0 += BK) {
        // load A tile (64 rows x 32 cols) transposed into As[k][m]
#pragma unroll
        for (int l = tid; l < BM * BK / 4; l += 256) {
            int r  = l >> 3;          // 0..63
            int c4 = l & 7;           // 0..7
            int gr = block_row + r;
            float4 v = make_float4(0.f, 0.f, 0.f, 0.f);
            if (gr < N_NODES) v = *(const float4*)&x[gr * IN_C + k0 + c4 * 4];
            As[c4 * 4 + 0][r] = v.x;
            As[c4 * 4 + 1][r] = v.y;
            As[c4 * 4 + 2][r] = v.z;
            As[c4 * 4 + 3][r] = v.w;
        }
        // load B tile: Bs[k][n] = W0[n][k0+k]
#pragma unroll
        for (int l = tid; l < BN * BK / 4; l += 256) {
            int n  = l >> 3;          // 0..127
            int c4 = l & 7;
            float4 v = *(const float4*)&W0[n * IN_C + k0 + c4 * 4];
            Bs[c4 * 4 + 0][n] = v.x;
            Bs[c4 * 4 + 1][n] = v.y;
            Bs[c4 * 4 + 2][n] = v.z;
            Bs[c4 * 4 + 3][n] = v.w;
        }
        __syncthreads();
#pragma unroll
        for (int kk = 0; kk < BK; kk++) {
            float4 a0 = *(float4*)&As[kk][trow * 8];
            float4 a1 = *(float4*)&As[kk][trow * 8 + 4];
            float4 b  = *(float4*)&Bs[kk][tcol * 4];
            float a[8] = {a0.x, a0.y, a0.z, a0.w, a1.x, a1.y, a1.z, a1.w};
            float bb[4] = {b.x, b.y, b.z, b.w};
#pragma unroll
            for (int i = 0; i < 8; i++)
#pragma unroll
                for (int j = 0; j < 4; j++) acc[i][j] += a[i] * bb[j];
        }
        __syncthreads();
    }
#pragma unroll
    for (int i = 0; i < 8; i++) {
        int gr = block_row + trow * 8 + i;
        if (gr < N_NODES) {
            float4 v = make_float4(acc[i][0], acc[i][1], acc[i][2], acc[i][3]);
            *(float4*)&g_h0[gr * HID_C + tcol * 4] = v;
        }
    }
}

// ---------------- agg0: warp per edge, 128 channels via float4 ----------------
__global__ __launch_bounds__(256) void agg0_kernel() {
    int t = blockIdx.x * blockDim.x + threadIdx.x;
    int e = t >> 5;
    int lane = t & 31;
    if (e >= N_EDGES) return;
    int s = g_src[e];
    int d = g_dst[e];
    float w = g_w[e];
    float4 v = *(const float4*)&g_h0[s * HID_C + lane * 4];
    v.x *= w; v.y *= w; v.z *= w; v.w *= w;
    atomicAdd((float4*)&g_agg0[d * HID_C + lane * 4], v);
}

// ---------------- GEMM1 fused relu+bias: h1[N,40] = relu(agg0+b0) @ W1^T ----------------
__global__ __launch_bounds__(128) void gemm1_kernel(const float* __restrict__ b0,
                                                    const float* __restrict__ W1) {
    __shared__ float sW[HID_C][OUT_C];   // [k][c], 20 KB
    __shared__ float sb0[HID_C];
    int tid = threadIdx.x;
    for (int l = tid; l < OUT_C * HID_C; l += 128) {
        int c = l / HID_C;
        int k = l - c * HID_C;
        sW[k][c] = W1[l];
    }
    if (tid < HID_C) sb0[tid] = b0[tid];
    __syncthreads();

    int r = blockIdx.x * 128 + tid;
    if (r >= N_NODES) return;

    float acc[OUT_C];
#pragma unroll
    for (int c = 0; c < OUT_C; c++) acc[c] = 0.f;

    const float4* arow = (const float4*)&g_agg0[r * HID_C];
#pragma unroll 4
    for (int k4 = 0; k4 < HID_C / 4; k4++) {
        float4 av = arow[k4];
        float a[4] = {av.x, av.y, av.z, av.w};
#pragma unroll
        for (int q = 0; q < 4; q++) {
            int k = k4 * 4 + q;
            float h = fmaxf(a[q] + sb0[k], 0.f);
#pragma unroll
            for (int c = 0; c < OUT_C; c += 4) {
                float4 wv = *(const float4*)&sW[k][c];
                acc[c + 0] += h * wv.x;
                acc[c + 1] += h * wv.y;
                acc[c + 2] += h * wv.z;
                acc[c + 3] += h * wv.w;
            }
        }
    }
    float* orow = &g_h1[r * OUT_C];
#pragma unroll
    for (int c = 0; c < OUT_C; c += 4)
        *(float4*)&orow[c] = make_float4(acc[c], acc[c + 1], acc[c + 2], acc[c + 3]);
}

// ---------------- agg1: thread per (edge, float4 chunk), 10 chunks/edge ----------------
__global__ __launch_bounds__(256) void agg1_kernel(float* __restrict__ out) {
    int g = blockIdx.x * blockDim.x + threadIdx.x;
    if (g >= N_EDGES * 10) return;
    int e = g / 10;
    int c = g - e * 10;
    int s = g_src[e];
    int d = g_dst[e];
    float w = g_w[e];
    float4 v = *(const float4*)&g_h1[s * OUT_C + c * 4];
    v.x *= w; v.y *= w; v.z *= w; v.w *= w;
    atomicAdd((float4*)&out[d * OUT_C + c * 4], v);
}

// ---------------- final bias ----------------
__global__ void bias_kernel(float* __restrict__ out, const float* __restrict__ b1) {
    int i = blockIdx.x * blockDim.x + threadIdx.x;
    if (i < N_NODES * OUT_C) {
        int c = i % OUT_C;
        out[i] += __ldg(&b1[c]);
    }
}

// ---------------- launch ----------------
extern "C" void kernel_launch(void* const* d_in, const int* in_sizes, int n_in,
                              void* d_out, int out_size) {
    const float* x  = (const float*)d_in[0];
    const int*   ei = (const int*)d_in[1];      // int32 (JAX default, x64 disabled)
    const float* W0 = (const float*)d_in[2];
    const float* b0 = (const float*)d_in[3];
    const float* W1 = (const float*)d_in[4];
    const float* b1 = (const float*)d_in[5];
    float* out = (float*)d_out;

    zero_all<<<2048, 256>>>((float4*)out);
    deg_kernel<<<(N_EDGES + 255) / 256, 256>>>(ei);
    dinv_kernel<<<(N_NODES + 255) / 256, 256>>>();
    prep_kernel<<<(N_EDGES + 255) / 256, 256>>>(ei);
    gemm0_kernel<<<(N_NODES + BM - 1) / BM, 256>>>(x, W0);
    {
        long long total = (long long)N_EDGES * 32;
        int blocks = (int)((total + 255) / 256);
        agg0_kernel<<<blocks, 256>>>();
    }
    gemm1_kernel<<<(N_NODES + 127) / 128, 128>>>(b0, W1);
    agg1_kernel<<<(N_EDGES * 10 + 255) / 256, 256>>>(out);
    bias_kernel<<<(N_NODES * OUT_C + 255) / 256, 256>>>(out, b1);
}

// round 3
// speedup vs baseline: 1.0322x; 1.0322x over previous
#include <cuda_runtime.h>

#define N_NODES 100000
#define N_EDGES 1600000
#define IN_C    512
#define HID_C   128
#define OUT_C   40

// ---------------- scratch (device globals; no allocations) ----------------
__device__ float g_deg[N_NODES];
__device__ int   g_src[N_EDGES];
__device__ int   g_dst[N_EDGES];
__device__ float g_w[N_EDGES];
__device__ float g_h0[N_NODES * HID_C];     // 51.2 MB
__device__ float g_agg0[N_NODES * HID_C];   // 51.2 MB
__device__ float g_h1[N_NODES * OUT_C];     // 16 MB

// ---------------- packed f32x2 helpers (Blackwell FFMA2) ----------------
__device__ __forceinline__ unsigned long long pack2(float x, float y) {
    unsigned long long r;
    asm("mov.b64 %0, {%1, %2};" : "=l"(r) : "f"(x), "f"(y));
    return r;
}
__device__ __forceinline__ void unpack2(unsigned long long v, float& x, float& y) {
    asm("mov.b64 {%0, %1}, %2;" : "=f"(x), "=f"(y) : "l"(v));
}
__device__ __forceinline__ void ffma2(unsigned long long& acc, unsigned long long a,
                                      unsigned long long b) {
    asm("fma.rn.f32x2 %0, %1, %2, %3;" : "=l"(acc) : "l"(a), "l"(b), "l"(acc));
}

// ---------------- zero scratch + init output with bias b1 ----------------
__global__ void zero_all(float4* __restrict__ out, const float4* __restrict__ b1v) {
    __shared__ float4 sb[10];                 // 40 channels = 10 float4
    if (threadIdx.x < 10) sb[threadIdx.x] = b1v[threadIdx.x];
    __syncthreads();
    int i = blockIdx.x * blockDim.x + threadIdx.x;
    int stride = gridDim.x * blockDim.x;
    float4 z = make_float4(0.f, 0.f, 0.f, 0.f);
    float4* agg = (float4*)g_agg0;
    for (int j = i; j < N_NODES * HID_C / 4; j += stride) agg[j] = z;
    for (int j = i; j < N_NODES * OUT_C / 4; j += stride) out[j] = sb[j % 10];
    float4* dg = (float4*)g_deg;
    for (int j = i; j < N_NODES / 4; j += stride) dg[j] = z;
}

// ---------------- degree (in-degree over dst, as in reference) ----------------
// edge_index is int32 [2, N_EDGES]: src = ei[e], dst = ei[N_EDGES + e]
__global__ void deg_kernel(const int* __restrict__ ei) {
    int e = blockIdx.x * blockDim.x + threadIdx.x;
    if (e < N_EDGES) {
        unsigned d = (unsigned)ei[N_EDGES + e];
        if (d < N_NODES) atomicAdd(&g_deg[d], 1.0f);
    }
}

__global__ void dinv_kernel() {
    int i = blockIdx.x * blockDim.x + threadIdx.x;
    if (i < N_NODES) g_deg[i] = rsqrtf(fmaxf(g_deg[i], 1.0f));
}

// int32 indices copied + per-edge weight (shared by both conv layers)
__global__ void prep_kernel(const int* __restrict__ ei) {
    int e = blockIdx.x * blockDim.x + threadIdx.x;
    if (e < N_EDGES) {
        unsigned s = (unsigned)ei[e];
        unsigned d = (unsigned)ei[N_EDGES + e];
        if (s >= N_NODES) s = 0;   // safety: fail via rel_err, not a fault
        if (d >= N_NODES) d = 0;
        g_src[e] = (int)s;
        g_dst[e] = (int)d;
        g_w[e] = g_deg[s] * g_deg[d];
    }
}

// ---------------- GEMM0: h0[N,128] = x[N,512] @ W0[128,512]^T ----------------
// BM=64, BN=128, BK=32, 256 threads, 8x4 micro-tile per thread, FFMA2 inner loop.
#define BM 64
#define BN 128
#define BK 32
__global__ __launch_bounds__(256) void gemm0_kernel(const float* __restrict__ x,
                                                    const float* __restrict__ W0) {
    __shared__ float As[BK][BM];      // transposed A tile, 8 KB
    __shared__ float Bs[BK][BN];      // 16 KB
    int block_row = blockIdx.x * BM;
    int tid  = threadIdx.x;
    int tcol = tid & 31;              // 32 col-groups of 4
    int trow = tid >> 5;              // 8 row-groups of 8

    // acc2[p][j]: p = M-pair (rows trow*8+2p, +2p+1), j = N column
    unsigned long long acc2[4][4];
#pragma unroll
    for (int p = 0; p < 4; p++)
#pragma unroll
        for (int j = 0; j < 4; j++) acc2[p][j] = 0ull;   // two packed +0.0f

    for (int k0 = 0; k0 < IN_C; k0 += BK) {
        // load A tile (64 rows x 32 cols) transposed into As[k][m]
#pragma unroll
        for (int l = tid; l < BM * BK / 4; l += 256) {
            int r  = l >> 3;          // 0..63
            int c4 = l & 7;           // 0..7
            int gr = block_row + r;
            float4 v = make_float4(0.f, 0.f, 0.f, 0.f);
            if (gr < N_NODES) v = *(const float4*)&x[gr * IN_C + k0 + c4 * 4];
            As[c4 * 4 + 0][r] = v.x;
            As[c4 * 4 + 1][r] = v.y;
            As[c4 * 4 + 2][r] = v.z;
            As[c4 * 4 + 3][r] = v.w;
        }
        // load B tile: Bs[k][n] = W0[n][k0+k]
#pragma unroll
        for (int l = tid; l < BN * BK / 4; l += 256) {
            int n  = l >> 3;          // 0..127
            int c4 = l & 7;
            float4 v = *(const float4*)&W0[n * IN_C + k0 + c4 * 4];
            Bs[c4 * 4 + 0][n] = v.x;
            Bs[c4 * 4 + 1][n] = v.y;
            Bs[c4 * 4 + 2][n] = v.z;
            Bs[c4 * 4 + 3][n] = v.w;
        }
        __syncthreads();
#pragma unroll
        for (int kk = 0; kk < BK; kk++) {
            float4 a0 = *(float4*)&As[kk][trow * 8];
            float4 a1 = *(float4*)&As[kk][trow * 8 + 4];
            float4 b  = *(float4*)&Bs[kk][tcol * 4];
            unsigned long long ap[4] = {pack2(a0.x, a0.y), pack2(a0.z, a0.w),
                                        pack2(a1.x, a1.y), pack2(a1.z, a1.w)};
            unsigned long long bj[4] = {pack2(b.x, b.x), pack2(b.y, b.y),
                                        pack2(b.z, b.z), pack2(b.w, b.w)};
#pragma unroll
            for (int p = 0; p < 4; p++)
#pragma unroll
                for (int j = 0; j < 4; j++) ffma2(acc2[p][j], ap[p], bj[j]);
        }
        __syncthreads();
    }
#pragma unroll
    for (int p = 0; p < 4; p++) {
        float lo[4], hi[4];
#pragma unroll
        for (int j = 0; j < 4; j++) unpack2(acc2[p][j], lo[j], hi[j]);
        int gr0 = block_row + trow * 8 + 2 * p;
        if (gr0 < N_NODES)
            *(float4*)&g_h0[gr0 * HID_C + tcol * 4] =
                make_float4(lo[0], lo[1], lo[2], lo[3]);
        if (gr0 + 1 < N_NODES)
            *(float4*)&g_h0[(gr0 + 1) * HID_C + tcol * 4] =
                make_float4(hi[0], hi[1], hi[2], hi[3]);
    }
}

// ---------------- agg0: warp per edge, 128 channels via float4 ----------------
__global__ __launch_bounds__(256) void agg0_kernel() {
    int t = blockIdx.x * blockDim.x + threadIdx.x;
    int e = t >> 5;
    int lane = t & 31;
    if (e >= N_EDGES) return;
    int s = g_src[e];
    int d = g_dst[e];
    float w = g_w[e];
    float4 v = *(const float4*)&g_h0[s * HID_C + lane * 4];
    v.x *= w; v.y *= w; v.z *= w; v.w *= w;
    atomicAdd((float4*)&g_agg0[d * HID_C + lane * 4], v);
}

// ---------------- GEMM1 fused relu+bias: h1[N,40] = relu(agg0+b0) @ W1^T ----------------
__global__ __launch_bounds__(128) void gemm1_kernel(const float* __restrict__ b0,
                                                    const float* __restrict__ W1) {
    __shared__ __align__(16) float sW[HID_C][OUT_C];   // [k][c], 20 KB
    __shared__ float sb0[HID_C];
    int tid = threadIdx.x;
    for (int l = tid; l < OUT_C * HID_C; l += 128) {
        int c = l / HID_C;
        int k = l - c * HID_C;
        sW[k][c] = W1[l];
    }
    if (tid < HID_C) sb0[tid] = b0[tid];
    __syncthreads();

    int r = blockIdx.x * 128 + tid;
    if (r >= N_NODES) return;

    unsigned long long acc2[OUT_C / 2];    // pairs over output channel
#pragma unroll
    for (int c = 0; c < OUT_C / 2; c++) acc2[c] = 0ull;

    const float4* arow = (const float4*)&g_agg0[r * HID_C];
#pragma unroll 4
    for (int k4 = 0; k4 < HID_C / 4; k4++) {
        float4 av = arow[k4];
        float a[4] = {av.x, av.y, av.z, av.w};
#pragma unroll
        for (int q = 0; q < 4; q++) {
            int k = k4 * 4 + q;
            float h = fmaxf(a[q] + sb0[k], 0.f);
            unsigned long long hb = pack2(h, h);
            const float2* wrow = (const float2*)&sW[k][0];
#pragma unroll
            for (int c = 0; c < OUT_C / 2; c++) {
                float2 wv = wrow[c];
                ffma2(acc2[c], hb, pack2(wv.x, wv.y));
            }
        }
    }
    float* orow = &g_h1[r * OUT_C];
#pragma unroll
    for (int c = 0; c < OUT_C / 2; c += 2) {
        float x0, y0, x1, y1;
        unpack2(acc2[c], x0, y0);
        unpack2(acc2[c + 1], x1, y1);
        *(float4*)&orow[c * 2] = make_float4(x0, y0, x1, y1);
    }
}

// ---------------- agg1: thread per (edge, float4 chunk), 10 chunks/edge ----------------
// accumulates directly into out (pre-initialized with b1)
__global__ __launch_bounds__(256) void agg1_kernel(float* __restrict__ out) {
    int g = blockIdx.x * blockDim.x + threadIdx.x;
    if (g >= N_EDGES * 10) return;
    int e = g / 10;
    int c = g - e * 10;
    int s = g_src[e];
    int d = g_dst[e];
    float w = g_w[e];
    float4 v = *(const float4*)&g_h1[s * OUT_C + c * 4];
    v.x *= w; v.y *= w; v.z *= w; v.w *= w;
    atomicAdd((float4*)&out[d * OUT_C + c * 4], v);
}

// ---------------- launch ----------------
extern "C" void kernel_launch(void* const* d_in, const int* in_sizes, int n_in,
                              void* d_out, int out_size) {
    const float* x  = (const float*)d_in[0];
    const int*   ei = (const int*)d_in[1];      // int32 (JAX default, x64 disabled)
    const float* W0 = (const float*)d_in[2];
    const float* b0 = (const float*)d_in[3];
    const float* W1 = (const float*)d_in[4];
    const float* b1 = (const float*)d_in[5];
    float* out = (float*)d_out;

    zero_all<<<2048, 256>>>((float4*)out, (const float4*)b1);
    deg_kernel<<<(N_EDGES + 255) / 256, 256>>>(ei);
    dinv_kernel<<<(N_NODES + 255) / 256, 256>>>();
    prep_kernel<<<(N_EDGES + 255) / 256, 256>>>(ei);
    gemm0_kernel<<<(N_NODES + BM - 1) / BM, 256>>>(x, W0);
    {
        long long total = (long long)N_EDGES * 32;
        int blocks = (int)((total + 255) / 256);
        agg0_kernel<<<blocks, 256>>>();
    }
    gemm1_kernel<<<(N_NODES + 127) / 128, 128>>>(b0, W1);
    agg1_kernel<<<(N_EDGES * 10 + 255) / 256, 256>>>(out);
}

// round 4
// speedup vs baseline: 1.1722x; 1.1356x over previous
#include <cuda_runtime.h>

#define N_NODES 100000
#define N_EDGES 1600000
#define IN_C    512
#define HID_C   128
#define OUT_C   40

#define SCAN_BLOCKS 391   // ceil(100000/256)

// ---------------- scratch (device globals; no allocations) ----------------
__device__ int   g_cnt[N_NODES];          // in-degree histogram
__device__ int   g_fill[N_NODES];         // scatter cursors
__device__ int   g_row_off[N_NODES + 1];  // CSR row offsets
__device__ int   g_part[512];             // scan partials
__device__ float g_dinv[N_NODES];
__device__ int2  g_edge[N_EDGES];         // sorted-by-dst: (src, bitcast weight)
__device__ float g_h0[N_NODES * HID_C];   // 51.2 MB
__device__ float g_agg0[N_NODES * HID_C]; // 51.2 MB
__device__ float g_h1[N_NODES * OUT_C];   // 16 MB

// ---------------- packed f32x2 helpers ----------------
typedef unsigned long long u64;
__device__ __forceinline__ u64 pack2(float x, float y) {
    u64 r;
    asm("mov.b64 %0, {%1, %2};" : "=l"(r) : "f"(x), "f"(y));
    return r;
}
__device__ __forceinline__ void unpack2(u64 v, float& x, float& y) {
    asm("mov.b64 {%0, %1}, %2;" : "=f"(x), "=f"(y) : "l"(v));
}
__device__ __forceinline__ void ffma2(u64& acc, u64 a, u64 b) {
    asm("fma.rn.f32x2 %0, %1, %2, %3;" : "=l"(acc) : "l"(a), "l"(b), "l"(acc));
}

// ---------------- zero counters ----------------
__global__ void zero_cnt_kernel() {
    int i = blockIdx.x * blockDim.x + threadIdx.x;
    if (i < N_NODES) { g_cnt[i] = 0; g_fill[i] = 0; }
}

// ---------------- histogram of dst (in-degree) ----------------
__global__ void hist_kernel(const int* __restrict__ ei) {
    int e = blockIdx.x * blockDim.x + threadIdx.x;
    if (e < N_EDGES) {
        unsigned d = (unsigned)ei[N_EDGES + e];
        if (d < N_NODES) atomicAdd(&g_cnt[d], 1);
    }
}

__global__ void dinv_kernel() {
    int i = blockIdx.x * blockDim.x + threadIdx.x;
    if (i < N_NODES) g_dinv[i] = rsqrtf(fmaxf((float)g_cnt[i], 1.0f));
}

// ---------------- 3-kernel exclusive scan of g_cnt -> g_row_off ----------------
__global__ void scan1_kernel() {
    __shared__ int sh[256];
    int t = threadIdx.x;
    int i = blockIdx.x * 256 + t;
    int v = (i < N_NODES) ? g_cnt[i] : 0;
    sh[t] = v;
    __syncthreads();
#pragma unroll
    for (int o = 1; o < 256; o <<= 1) {
        int add = (t >= o) ? sh[t - o] : 0;
        __syncthreads();
        sh[t] += add;
        __syncthreads();
    }
    if (i < N_NODES) g_row_off[i] = sh[t] - v;  // exclusive within block
    if (t == 255) g_part[blockIdx.x] = sh[255];
}

__global__ void scan2_kernel() {
    __shared__ int sh[512];
    int t = threadIdx.x;
    int v = (t < SCAN_BLOCKS) ? g_part[t] : 0;
    sh[t] = v;
    __syncthreads();
#pragma unroll
    for (int o = 1; o < 512; o <<= 1) {
        int add = (t >= o) ? sh[t - o] : 0;
        __syncthreads();
        sh[t] += add;
        __syncthreads();
    }
    if (t < SCAN_BLOCKS) g_part[t] = sh[t] - v;  // exclusive block offsets
}

__global__ void scan3_kernel() {
    int i = blockIdx.x * blockDim.x + threadIdx.x;
    if (i < N_NODES) {
        int base = g_row_off[i] + g_part[i >> 8];
        g_row_off[i] = base;
        if (i == N_NODES - 1) g_row_off[N_NODES] = base + g_cnt[i];
    }
}

// ---------------- scatter edges into CSR (sorted by dst) ----------------
__global__ void scatter_kernel(const int* __restrict__ ei) {
    int e = blockIdx.x * blockDim.x + threadIdx.x;
    if (e < N_EDGES) {
        unsigned s = (unsigned)ei[e];
        unsigned d = (unsigned)ei[N_EDGES + e];
        if (s >= N_NODES) s = 0;
        if (d < N_NODES) {
            int pos = g_row_off[d] + atomicAdd(&g_fill[d], 1);
            float w = g_dinv[s] * g_dinv[d];
            g_edge[pos] = make_int2((int)s, __float_as_int(w));
        }
    }
}

// ---------------- GEMM0: h0[N,128] = x[N,512] @ W0[128,512]^T ----------------
// BM=128, BN=128, BK=16, 256 threads (16x16), 8x8 micro-tile, FFMA2 with
// duplicated-A smem so operands load pre-packed via LDS.64 (no mov packing).
#define G0_BM 128
#define G0_BN 128
#define G0_BK 16
__global__ __launch_bounds__(256) void gemm0_kernel(const float* __restrict__ x,
                                                    const float* __restrict__ W0) {
    __shared__ float AsD[G0_BK][2 * G0_BM];  // AsD[k][2m]=AsD[k][2m+1]=A[m][k], 16 KB
    __shared__ float Bs[G0_BK][G0_BN];       // Bs[k][n]=W0[n][k], 8 KB
    int tid = threadIdx.x;
    int tx = tid & 15;   // N dim
    int ty = tid >> 4;   // M dim
    int block_row = blockIdx.x * G0_BM;

    u64 acc2[8][4];      // [i = M row][q = N pair (cols tx*8+2q, +2q+1)]
#pragma unroll
    for (int i = 0; i < 8; i++)
#pragma unroll
        for (int q = 0; q < 4; q++) acc2[i][q] = 0ull;

    for (int k0 = 0; k0 < IN_C; k0 += G0_BK) {
        // A tile: 128 rows x 16 cols -> duplicated store
#pragma unroll
        for (int it = 0; it < 2; it++) {
            int l = tid + it * 256;
            int r  = l >> 2;          // 0..127
            int c4 = l & 3;           // 0..3 -> cols c4*4..+3
            int gr = block_row + r;
            float4 v = make_float4(0.f, 0.f, 0.f, 0.f);
            if (gr < N_NODES) v = *(const float4*)&x[gr * IN_C + k0 + c4 * 4];
            *(float2*)&AsD[c4 * 4 + 0][2 * r] = make_float2(v.x, v.x);
            *(float2*)&AsD[c4 * 4 + 1][2 * r] = make_float2(v.y, v.y);
            *(float2*)&AsD[c4 * 4 + 2][2 * r] = make_float2(v.z, v.z);
            *(float2*)&AsD[c4 * 4 + 3][2 * r] = make_float2(v.w, v.w);
        }
        // B tile: Bs[k][n] = W0[n][k0+k]
#pragma unroll
        for (int it = 0; it < 2; it++) {
            int l = tid + it * 256;
            int n  = l >> 2;
            int c4 = l & 3;
            float4 v = *(const float4*)&W0[n * IN_C + k0 + c4 * 4];
            Bs[c4 * 4 + 0][n] = v.x;
            Bs[c4 * 4 + 1][n] = v.y;
            Bs[c4 * 4 + 2][n] = v.z;
            Bs[c4 * 4 + 3][n] = v.w;
        }
        __syncthreads();
#pragma unroll
        for (int kk = 0; kk < G0_BK; kk++) {
            u64 a[8], b[4];
#pragma unroll
            for (int i = 0; i < 8; i++)
                a[i] = *(const u64*)&AsD[kk][(ty * 8 + i) * 2];   // (A, A) packed
#pragma unroll
            for (int q = 0; q < 4; q++)
                b[q] = *(const u64*)&Bs[kk][tx * 8 + 2 * q];      // (Bn, Bn+1)
#pragma unroll
            for (int i = 0; i < 8; i++)
#pragma unroll
                for (int q = 0; q < 4; q++) ffma2(acc2[i][q], a[i], b[q]);
        }
        __syncthreads();
    }
#pragma unroll
    for (int i = 0; i < 8; i++) {
        int gr = block_row + ty * 8 + i;
        if (gr < N_NODES) {
            float p0x, p0y, p1x, p1y, p2x, p2y, p3x, p3y;
            unpack2(acc2[i][0], p0x, p0y);
            unpack2(acc2[i][1], p1x, p1y);
            unpack2(acc2[i][2], p2x, p2y);
            unpack2(acc2[i][3], p3x, p3y);
            float* orow = &g_h0[gr * HID_C + tx * 8];
            *(float4*)&orow[0] = make_float4(p0x, p0y, p1x, p1y);
            *(float4*)&orow[4] = make_float4(p2x, p2y, p3x, p3y);
        }
    }
}

// ---------------- agg0: warp per node, CSR segment sum, no atomics ----------------
__global__ __launch_bounds__(256) void agg0_kernel() {
    int t = blockIdx.x * blockDim.x + threadIdx.x;
    int node = t >> 5;
    int lane = t & 31;
    if (node >= N_NODES) return;
    int beg = g_row_off[node];
    int end = g_row_off[node + 1];
    float4 acc = make_float4(0.f, 0.f, 0.f, 0.f);
    int j = beg;
    for (; j + 2 <= end; j += 2) {
        int2 e0 = g_edge[j];
        int2 e1 = g_edge[j + 1];
        float w0 = __int_as_float(e0.y);
        float w1 = __int_as_float(e1.y);
        float4 v0 = *(const float4*)&g_h0[e0.x * HID_C + lane * 4];
        float4 v1 = *(const float4*)&g_h0[e1.x * HID_C + lane * 4];
        acc.x += w0 * v0.x; acc.y += w0 * v0.y; acc.z += w0 * v0.z; acc.w += w0 * v0.w;
        acc.x += w1 * v1.x; acc.y += w1 * v1.y; acc.z += w1 * v1.z; acc.w += w1 * v1.w;
    }
    if (j < end) {
        int2 e0 = g_edge[j];
        float w0 = __int_as_float(e0.y);
        float4 v0 = *(const float4*)&g_h0[e0.x * HID_C + lane * 4];
        acc.x += w0 * v0.x; acc.y += w0 * v0.y; acc.z += w0 * v0.z; acc.w += w0 * v0.w;
    }
    *(float4*)&g_agg0[node * HID_C + lane * 4] = acc;
}

// ---------------- GEMM1 fused relu+bias: h1[N,40] = relu(agg0+b0) @ W1^T ----------------
__global__ __launch_bounds__(128) void gemm1_kernel(const float* __restrict__ b0,
                                                    const float* __restrict__ W1) {
    __shared__ __align__(16) float sW[HID_C][OUT_C];   // [k][c], 20 KB
    __shared__ float sb0[HID_C];
    int tid = threadIdx.x;
    for (int l = tid; l < OUT_C * HID_C; l += 128) {
        int c = l / HID_C;
        int k = l - c * HID_C;
        sW[k][c] = W1[l];
    }
    if (tid < HID_C) sb0[tid] = b0[tid];
    __syncthreads();

    int r = blockIdx.x * 128 + tid;
    if (r >= N_NODES) return;

    u64 acc2[OUT_C / 2];
#pragma unroll
    for (int c = 0; c < OUT_C / 2; c++) acc2[c] = 0ull;

    const float4* arow = (const float4*)&g_agg0[r * HID_C];
#pragma unroll 4
    for (int k4 = 0; k4 < HID_C / 4; k4++) {
        float4 av = arow[k4];
        float a[4] = {av.x, av.y, av.z, av.w};
#pragma unroll
        for (int q = 0; q < 4; q++) {
            int k = k4 * 4 + q;
            float h = fmaxf(a[q] + sb0[k], 0.f);
            u64 hb = pack2(h, h);
            const u64* wrow = (const u64*)&sW[k][0];   // rows are 8B-aligned (160 B)
#pragma unroll
            for (int c = 0; c < OUT_C / 2; c++) ffma2(acc2[c], hb, wrow[c]);
        }
    }
    float* orow = &g_h1[r * OUT_C];
#pragma unroll
    for (int c = 0; c < OUT_C / 2; c += 2) {
        float x0, y0, x1, y1;
        unpack2(acc2[c], x0, y0);
        unpack2(acc2[c + 1], x1, y1);
        *(float4*)&orow[c * 2] = make_float4(x0, y0, x1, y1);
    }
}

// ---------------- agg1: warp per node (lanes 0-9), writes bias + sum ----------------
__global__ __launch_bounds__(256) void agg1_kernel(float* __restrict__ out,
                                                   const float4* __restrict__ b1v) {
    int t = blockIdx.x * blockDim.x + threadIdx.x;
    int node = t >> 5;
    int lane = t & 31;
    if (node >= N_NODES || lane >= 10) return;
    int beg = g_row_off[node];
    int end = g_row_off[node + 1];
    float4 acc = b1v[lane];
    int j = beg;
    for (; j + 2 <= end; j += 2) {
        int2 e0 = g_edge[j];
        int2 e1 = g_edge[j + 1];
        float w0 = __int_as_float(e0.y);
        float w1 = __int_as_float(e1.y);
        float4 v0 = *(const float4*)&g_h1[e0.x * OUT_C + lane * 4];
        float4 v1 = *(const float4*)&g_h1[e1.x * OUT_C + lane * 4];
        acc.x += w0 * v0.x; acc.y += w0 * v0.y; acc.z += w0 * v0.z; acc.w += w0 * v0.w;
        acc.x += w1 * v1.x; acc.y += w1 * v1.y; acc.z += w1 * v1.z; acc.w += w1 * v1.w;
    }
    if (j < end) {
        int2 e0 = g_edge[j];
        float w0 = __int_as_float(e0.y);
        float4 v0 = *(const float4*)&g_h1[e0.x * OUT_C + lane * 4];
        acc.x += w0 * v0.x; acc.y += w0 * v0.y; acc.z += w0 * v0.z; acc.w += w0 * v0.w;
    }
    *(float4*)&out[node * OUT_C + lane * 4] = acc;
}

// ---------------- launch ----------------
extern "C" void kernel_launch(void* const* d_in, const int* in_sizes, int n_in,
                              void* d_out, int out_size) {
    const float* x  = (const float*)d_in[0];
    const int*   ei = (const int*)d_in[1];      // int32 [2, N_EDGES]
    const float* W0 = (const float*)d_in[2];
    const float* b0 = (const float*)d_in[3];
    const float* W1 = (const float*)d_in[4];
    const float* b1 = (const float*)d_in[5];
    float* out = (float*)d_out;

    zero_cnt_kernel<<<SCAN_BLOCKS, 256>>>();
    hist_kernel<<<(N_EDGES + 255) / 256, 256>>>(ei);
    dinv_kernel<<<SCAN_BLOCKS, 256>>>();
    scan1_kernel<<<SCAN_BLOCKS, 256>>>();
    scan2_kernel<<<1, 512>>>();
    scan3_kernel<<<SCAN_BLOCKS, 256>>>();
    scatter_kernel<<<(N_EDGES + 255) / 256, 256>>>(ei);
    gemm0_kernel<<<(N_NODES + G0_BM - 1) / G0_BM, 256>>>(x, W0);
    agg0_kernel<<<(N_NODES * 32 + 255) / 256, 256>>>();
    gemm1_kernel<<<(N_NODES + 127) / 128, 128>>>(b0, W1);
    agg1_kernel<<<(N_NODES * 32 + 255) / 256, 256>>>(out, (const float4*)b1);
}

// round 6
// speedup vs baseline: 1.8294x; 1.5606x over previous
#include <cuda_runtime.h>
#include <cuda_bf16.h>
#include <cstdint>

#define N_NODES 100000
#define N_EDGES 1600000
#define IN_C    512
#define HID_C   128
#define OUT_C   40

#define SCAN_BLOCKS 391   // ceil(100000/256)

// ---------------- scratch (device globals; no allocations) ----------------
__device__ int   g_cnt[N_NODES];
__device__ int   g_fill[N_NODES];
__device__ int   g_row_off[N_NODES + 1];
__device__ int   g_part[512];
__device__ float g_dinv[N_NODES];
__device__ int2  g_edge[N_EDGES];
__device__ float g_h0[N_NODES * HID_C];   // 51.2 MB
__device__ float g_agg0[N_NODES * HID_C]; // 51.2 MB
__device__ float g_h1[N_NODES * OUT_C];   // 16 MB

typedef unsigned long long u64;

// ---------------- packed f32x2 helpers (for gemm1) ----------------
__device__ __forceinline__ u64 pack2(float x, float y) {
    u64 r;
    asm("mov.b64 %0, {%1, %2};" : "=l"(r) : "f"(x), "f"(y));
    return r;
}
__device__ __forceinline__ void unpack2(u64 v, float& x, float& y) {
    asm("mov.b64 {%0, %1}, %2;" : "=f"(x), "=f"(y) : "l"(v));
}
__device__ __forceinline__ void ffma2(u64& acc, u64 a, u64 b) {
    asm("fma.rn.f32x2 %0, %1, %2, %3;" : "=l"(acc) : "l"(a), "l"(b), "l"(acc));
}

__device__ __forceinline__ uint32_t smem_u32(const void* p) {
    uint32_t a;
    asm("{ .reg .u64 t; cvta.to.shared.u64 t, %1; cvt.u32.u64 %0, t; }" : "=r"(a) : "l"(p));
    return a;
}

// ---------------- setup kernels ----------------
__global__ void zero_cnt_kernel() {
    int i = blockIdx.x * blockDim.x + threadIdx.x;
    if (i < N_NODES) { g_cnt[i] = 0; g_fill[i] = 0; }
}

__global__ void hist_kernel(const int* __restrict__ ei) {
    int e = blockIdx.x * blockDim.x + threadIdx.x;
    if (e < N_EDGES) {
        unsigned d = (unsigned)ei[N_EDGES + e];
        if (d < N_NODES) atomicAdd(&g_cnt[d], 1);
    }
}

__global__ void dinv_kernel() {
    int i = blockIdx.x * blockDim.x + threadIdx.x;
    if (i < N_NODES) g_dinv[i] = rsqrtf(fmaxf((float)g_cnt[i], 1.0f));
}

__global__ void scan1_kernel() {
    __shared__ int sh[256];
    int t = threadIdx.x;
    int i = blockIdx.x * 256 + t;
    int v = (i < N_NODES) ? g_cnt[i] : 0;
    sh[t] = v;
    __syncthreads();
#pragma unroll
    for (int o = 1; o < 256; o <<= 1) {
        int add = (t >= o) ? sh[t - o] : 0;
        __syncthreads();
        sh[t] += add;
        __syncthreads();
    }
    if (i < N_NODES) g_row_off[i] = sh[t] - v;
    if (t == 255) g_part[blockIdx.x] = sh[255];
}

__global__ void scan2_kernel() {
    __shared__ int sh[512];
    int t = threadIdx.x;
    int v = (t < SCAN_BLOCKS) ? g_part[t] : 0;
    sh[t] = v;
    __syncthreads();
#pragma unroll
    for (int o = 1; o < 512; o <<= 1) {
        int add = (t >= o) ? sh[t - o] : 0;
        __syncthreads();
        sh[t] += add;
        __syncthreads();
    }
    if (t < SCAN_BLOCKS) g_part[t] = sh[t] - v;
}

__global__ void scan3_kernel() {
    int i = blockIdx.x * blockDim.x + threadIdx.x;
    if (i < N_NODES) {
        int base = g_row_off[i] + g_part[i >> 8];
        g_row_off[i] = base;
        if (i == N_NODES - 1) g_row_off[N_NODES] = base + g_cnt[i];
    }
}

__global__ void scatter_kernel(const int* __restrict__ ei) {
    int e = blockIdx.x * blockDim.x + threadIdx.x;
    if (e < N_EDGES) {
        unsigned s = (unsigned)ei[e];
        unsigned d = (unsigned)ei[N_EDGES + e];
        if (s >= N_NODES) s = 0;
        if (d < N_NODES) {
            int pos = g_row_off[d] + atomicAdd(&g_fill[d], 1);
            float w = g_dinv[s] * g_dinv[d];
            g_edge[pos] = make_int2((int)s, __float_as_int(w));
        }
    }
}

// ---------------- GEMM0 via mma.sync bf16x3 split ----------------
// h0[N,128] = x[N,512] @ W0[128,512]^T, fp32 accum, error-free to ~2^-16.
// CTA 128x128, 256 threads = 8 warps (4 m x 2 n), warp tile 32x64.
// Smem: bf16 hi/lo tiles [128 rows][64 k], 128B rows, XOR-16B swizzle.
#define SA_HI 0
#define SA_LO 16384
#define SB_HI 32768
#define SB_LO 49152
#define G0_SMEM 65536

#define SWZ(row, kb) (((row) * 128 + (kb)) ^ (((row) & 7) << 4))

// split float4 -> packed bf16x4 hi and lo (lo = residual)
__device__ __forceinline__ void split_f4(float4 v, u64& hi64, u64& lo64) {
    uint32_t hxy, hzw, lxy, lzw;
    asm("cvt.rn.bf16x2.f32 %0, %1, %2;" : "=r"(hxy) : "f"(v.y), "f"(v.x));
    asm("cvt.rn.bf16x2.f32 %0, %1, %2;" : "=r"(hzw) : "f"(v.w), "f"(v.z));
    float rx = v.x - __uint_as_float(hxy << 16);
    float ry = v.y - __uint_as_float(hxy & 0xFFFF0000u);
    float rz = v.z - __uint_as_float(hzw << 16);
    float rw = v.w - __uint_as_float(hzw & 0xFFFF0000u);
    asm("cvt.rn.bf16x2.f32 %0, %1, %2;" : "=r"(lxy) : "f"(ry), "f"(rx));
    asm("cvt.rn.bf16x2.f32 %0, %1, %2;" : "=r"(lzw) : "f"(rw), "f"(rz));
    hi64 = (u64)hxy | ((u64)hzw << 32);
    lo64 = (u64)lxy | ((u64)lzw << 32);
}

#define LDSM_X4(r0, r1, r2, r3, addr) \
    asm volatile("ldmatrix.sync.aligned.m8n8.x4.shared.b16 {%0,%1,%2,%3}, [%4];" \
                 : "=r"(r0), "=r"(r1), "=r"(r2), "=r"(r3) : "r"(addr))

#define MMA16816(c, a0, a1, a2, a3, b0, b1) \
    asm volatile("mma.sync.aligned.m16n8k16.row.col.f32.bf16.bf16.f32 " \
                 "{%0,%1,%2,%3}, {%4,%5,%6,%7}, {%8,%9}, {%0,%1,%2,%3};" \
                 : "+f"((c)[0]), "+f"((c)[1]), "+f"((c)[2]), "+f"((c)[3]) \
                 : "r"(a0), "r"(a1), "r"(a2), "r"(a3), "r"(b0), "r"(b1))

__global__ __launch_bounds__(256) void gemm0_mma_kernel(const float* __restrict__ x,
                                                        const float* __restrict__ W0) {
    extern __shared__ char smem[];
    uint32_t sbase = smem_u32(smem);
    int tid = threadIdx.x;
    int lane = tid & 31;
    int wid = tid >> 5;
    int warp_m = wid & 3;            // 4 m-warps * 32 rows
    int warp_n = wid >> 2;           // 2 n-warps * 64 cols
    int block_row = blockIdx.x * 128;

    float acc[2][8][4];
#pragma unroll
    for (int mt = 0; mt < 2; mt++)
#pragma unroll
        for (int nt = 0; nt < 8; nt++)
#pragma unroll
            for (int q = 0; q < 4; q++) acc[mt][nt][q] = 0.f;

    // ldmatrix lane addressing (precomputed components)
    int a_row_in = (lane & 7) + ((lane & 8) ? 8 : 0);
    int a_kb_in  = (lane & 16) ? 16 : 0;
    int b_row_in = (lane & 7) + ((lane & 16) ? 8 : 0);
    int b_kb_in  = (lane & 8) ? 16 : 0;

    for (int chunk = 0; chunk < 8; chunk++) {
        int k0 = chunk * 64;
        // --- load + split A tile (128 x 64 f32) ---
#pragma unroll
        for (int i = 0; i < 8; i++) {
            int idx = tid + 256 * i;
            int row = idx >> 4;
            int c4  = idx & 15;
            int gr  = block_row + row;
            float4 v = make_float4(0.f, 0.f, 0.f, 0.f);
            if (gr < N_NODES) v = *(const float4*)&x[(size_t)gr * IN_C + k0 + c4 * 4];
            u64 hi64, lo64;
            split_f4(v, hi64, lo64);
            uint32_t off = SWZ(row, c4 * 8);
            *(u64*)(smem + SA_HI + off) = hi64;
            *(u64*)(smem + SA_LO + off) = lo64;
        }
        // --- load + split B tile: W0[n][k0..k0+63] ---
#pragma unroll
        for (int i = 0; i < 8; i++) {
            int idx = tid + 256 * i;
            int n  = idx >> 4;
            int c4 = idx & 15;
            float4 v = *(const float4*)&W0[(size_t)n * IN_C + k0 + c4 * 4];
            u64 hi64, lo64;
            split_f4(v, hi64, lo64);
            uint32_t off = SWZ(n, c4 * 8);
            *(u64*)(smem + SB_HI + off) = hi64;
            *(u64*)(smem + SB_LO + off) = lo64;
        }
        __syncthreads();

#pragma unroll
        for (int ks = 0; ks < 4; ks++) {
            int kb = ks * 32;
            // A fragments: 2 m-tiles, hi+lo
            uint32_t ahi[2][4], alo[2][4];
#pragma unroll
            for (int mt = 0; mt < 2; mt++) {
                int row = warp_m * 32 + mt * 16 + a_row_in;
                uint32_t off = SWZ(row, kb + a_kb_in);
                LDSM_X4(ahi[mt][0], ahi[mt][1], ahi[mt][2], ahi[mt][3], sbase + SA_HI + off);
                LDSM_X4(alo[mt][0], alo[mt][1], alo[mt][2], alo[mt][3], sbase + SA_LO + off);
            }
            // B fragments: 8 n-tiles (2 per ldmatrix.x4), hi+lo
            uint32_t bhi[8][2], blo[8][2];
#pragma unroll
            for (int q = 0; q < 4; q++) {
                int row = warp_n * 64 + q * 16 + b_row_in;
                uint32_t off = SWZ(row, kb + b_kb_in);
                uint32_t r0, r1, r2, r3;
                LDSM_X4(r0, r1, r2, r3, sbase + SB_HI + off);
                bhi[q * 2][0] = r0; bhi[q * 2][1] = r1;
                bhi[q * 2 + 1][0] = r2; bhi[q * 2 + 1][1] = r3;
                LDSM_X4(r0, r1, r2, r3, sbase + SB_LO + off);
                blo[q * 2][0] = r0; blo[q * 2][1] = r1;
                blo[q * 2 + 1][0] = r2; blo[q * 2 + 1][1] = r3;
            }
            // 3-term MMA: hi*hi + hi*lo + lo*hi
#pragma unroll
            for (int mt = 0; mt < 2; mt++)
#pragma unroll
                for (int nt = 0; nt < 8; nt++) {
                    MMA16816(acc[mt][nt], ahi[mt][0], ahi[mt][1], ahi[mt][2], ahi[mt][3],
                             bhi[nt][0], bhi[nt][1]);
                    MMA16816(acc[mt][nt], ahi[mt][0], ahi[mt][1], ahi[mt][2], ahi[mt][3],
                             blo[nt][0], blo[nt][1]);
                    MMA16816(acc[mt][nt], alo[mt][0], alo[mt][1], alo[mt][2], alo[mt][3],
                             bhi[nt][0], bhi[nt][1]);
                }
        }
        __syncthreads();
    }

    // epilogue: acc -> g_h0
    int g  = lane >> 2;
    int tg = lane & 3;
#pragma unroll
    for (int mt = 0; mt < 2; mt++) {
        int row0 = block_row + warp_m * 32 + mt * 16 + g;
#pragma unroll
        for (int nt = 0; nt < 8; nt++) {
            int col = warp_n * 64 + nt * 8 + tg * 2;
            if (row0 < N_NODES)
                *(float2*)&g_h0[(size_t)row0 * HID_C + col] =
                    make_float2(acc[mt][nt][0], acc[mt][nt][1]);
            if (row0 + 8 < N_NODES)
                *(float2*)&g_h0[(size_t)(row0 + 8) * HID_C + col] =
                    make_float2(acc[mt][nt][2], acc[mt][nt][3]);
        }
    }
}

// ---------------- agg0: warp per node, CSR segment sum ----------------
__global__ __launch_bounds__(256) void agg0_kernel() {
    int t = blockIdx.x * blockDim.x + threadIdx.x;
    int node = t >> 5;
    int lane = t & 31;
    if (node >= N_NODES) return;
    int beg = g_row_off[node];
    int end = g_row_off[node + 1];
    float4 acc = make_float4(0.f, 0.f, 0.f, 0.f);
    int j = beg;
    for (; j + 2 <= end; j += 2) {
        int2 e0 = g_edge[j];
        int2 e1 = g_edge[j + 1];
        float w0 = __int_as_float(e0.y);
        float w1 = __int_as_float(e1.y);
        float4 v0 = *(const float4*)&g_h0[e0.x * HID_C + lane * 4];
        float4 v1 = *(const float4*)&g_h0[e1.x * HID_C + lane * 4];
        acc.x += w0 * v0.x; acc.y += w0 * v0.y; acc.z += w0 * v0.z; acc.w += w0 * v0.w;
        acc.x += w1 * v1.x; acc.y += w1 * v1.y; acc.z += w1 * v1.z; acc.w += w1 * v1.w;
    }
    if (j < end) {
        int2 e0 = g_edge[j];
        float w0 = __int_as_float(e0.y);
        float4 v0 = *(const float4*)&g_h0[e0.x * HID_C + lane * 4];
        acc.x += w0 * v0.x; acc.y += w0 * v0.y; acc.z += w0 * v0.z; acc.w += w0 * v0.w;
    }
    *(float4*)&g_agg0[node * HID_C + lane * 4] = acc;
}

// ---------------- GEMM1 fused relu+bias ----------------
__global__ __launch_bounds__(128) void gemm1_kernel(const float* __restrict__ b0,
                                                    const float* __restrict__ W1) {
    __shared__ __align__(16) float sW[HID_C][OUT_C];
    __shared__ float sb0[HID_C];
    int tid = threadIdx.x;
    for (int l = tid; l < OUT_C * HID_C; l += 128) {
        int c = l / HID_C;
        int k = l - c * HID_C;
        sW[k][c] = W1[l];
    }
    if (tid < HID_C) sb0[tid] = b0[tid];
    __syncthreads();

    int r = blockIdx.x * 128 + tid;
    if (r >= N_NODES) return;

    u64 acc2[OUT_C / 2];
#pragma unroll
    for (int c = 0; c < OUT_C / 2; c++) acc2[c] = 0ull;

    const float4* arow = (const float4*)&g_agg0[r * HID_C];
#pragma unroll 4
    for (int k4 = 0; k4 < HID_C / 4; k4++) {
        float4 av = arow[k4];
        float a[4] = {av.x, av.y, av.z, av.w};
#pragma unroll
        for (int q = 0; q < 4; q++) {
            int k = k4 * 4 + q;
            float h = fmaxf(a[q] + sb0[k], 0.f);
            u64 hb = pack2(h, h);
            const u64* wrow = (const u64*)&sW[k][0];
#pragma unroll
            for (int c = 0; c < OUT_C / 2; c++) ffma2(acc2[c], hb, wrow[c]);
        }
    }
    float* orow = &g_h1[r * OUT_C];
#pragma unroll
    for (int c = 0; c < OUT_C / 2; c += 2) {
        float x0, y0, x1, y1;
        unpack2(acc2[c], x0, y0);
        unpack2(acc2[c + 1], x1, y1);
        *(float4*)&orow[c * 2] = make_float4(x0, y0, x1, y1);
    }
}

// ---------------- agg1: warp per node (lanes 0-9), writes bias + sum ----------------
__global__ __launch_bounds__(256) void agg1_kernel(float* __restrict__ out,
                                                   const float4* __restrict__ b1v) {
    int t = blockIdx.x * blockDim.x + threadIdx.x;
    int node = t >> 5;
    int lane = t & 31;
    if (node >= N_NODES || lane >= 10) return;
    int beg = g_row_off[node];
    int end = g_row_off[node + 1];
    float4 acc = b1v[lane];
    int j = beg;
    for (; j + 2 <= end; j += 2) {
        int2 e0 = g_edge[j];
        int2 e1 = g_edge[j + 1];
        float w0 = __int_as_float(e0.y);
        float w1 = __int_as_float(e1.y);
        float4 v0 = *(const float4*)&g_h1[e0.x * OUT_C + lane * 4];
        float4 v1 = *(const float4*)&g_h1[e1.x * OUT_C + lane * 4];
        acc.x += w0 * v0.x; acc.y += w0 * v0.y; acc.z += w0 * v0.z; acc.w += w0 * v0.w;
        acc.x += w1 * v1.x; acc.y += w1 * v1.y; acc.z += w1 * v1.z; acc.w += w1 * v1.w;
    }
    if (j < end) {
        int2 e0 = g_edge[j];
        float w0 = __int_as_float(e0.y);
        float4 v0 = *(const float4*)&g_h1[e0.x * OUT_C + lane * 4];
        acc.x += w0 * v0.x; acc.y += w0 * v0.y; acc.z += w0 * v0.z; acc.w += w0 * v0.w;
    }
    *(float4*)&out[node * OUT_C + lane * 4] = acc;
}

// ---------------- launch ----------------
extern "C" void kernel_launch(void* const* d_in, const int* in_sizes, int n_in,
                              void* d_out, int out_size) {
    const float* x  = (const float*)d_in[0];
    const int*   ei = (const int*)d_in[1];
    const float* W0 = (const float*)d_in[2];
    const float* b0 = (const float*)d_in[3];
    const float* W1 = (const float*)d_in[4];
    const float* b1 = (const float*)d_in[5];
    float* out = (float*)d_out;

    cudaFuncSetAttribute(gemm0_mma_kernel, cudaFuncAttributeMaxDynamicSharedMemorySize, G0_SMEM);

    zero_cnt_kernel<<<SCAN_BLOCKS, 256>>>();
    hist_kernel<<<(N_EDGES + 255) / 256, 256>>>(ei);
    dinv_kernel<<<SCAN_BLOCKS, 256>>>();
    scan1_kernel<<<SCAN_BLOCKS, 256>>>();
    scan2_kernel<<<1, 512>>>();
    scan3_kernel<<<SCAN_BLOCKS, 256>>>();
    scatter_kernel<<<(N_EDGES + 255) / 256, 256>>>(ei);
    gemm0_mma_kernel<<<(N_NODES + 127) / 128, 256, G0_SMEM>>>(x, W0);
    agg0_kernel<<<(N_NODES * 32 + 255) / 256, 256>>>();
    gemm1_kernel<<<(N_NODES + 127) / 128, 128>>>(b0, W1);
    agg1_kernel<<<(N_NODES * 32 + 255) / 256, 256>>>(out, (const float4*)b1);
}